// round 12
// baseline (speedup 1.0000x reference)
#include <cuda_runtime.h>
#include <cuda_fp16.h>

#define NN 50000         // n_node
#define KP 8             // k_path
#define LP 6             // l_path
#define DN 64            // d_node
#define DP 128           // d_path
#define NE 1600000       // n_edge
#define PROJ_COLS 640    // (LP-1) * DP

// fp16 proj table (64 MB). proj[node][l*128+d]; row NN = zeros.
__device__ __half g_proj[(size_t)(NN + 1) * PROJ_COLS];
__device__ int g_is64;

// ---------------------------------------------------------------------------
// Phase 1 (tensor-core): proj[node][l*128+d] = sum_c feat16[node,c] * W16[d, l*64+c]
// Per CTA: 128 nodes (M) x 128 d (N), K=64, one l block (blockIdx.y).
// Block (0,0) warp 0 additionally sniffs the index dtype into g_is64.
// ---------------------------------------------------------------------------
#define TS 72   // smem row stride in halves (64 + 8 pad) -> conflict-free frags

__global__ void __launch_bounds__(256, 2) phase1_mma(
    const float* __restrict__ feat, const float* __restrict__ W,
    const unsigned int* __restrict__ paths_raw) {
  __shared__ __half As[128 * TS];   // [node][c]
  __shared__ __half Bs[128 * TS];   // [d][c]

  const int t = threadIdx.x;
  const int node0 = blockIdx.x * 128;
  const int l = blockIdx.y;

  // ---- dtype sniff (one warp, one block): int64 data has all-zero high words ----
  if (blockIdx.x == 0 && blockIdx.y == 0 && t < 32) {
    unsigned v = paths_raw[t * 2 + 1];
    unsigned any = __ballot_sync(0xFFFFFFFFu, v != 0u);
    if (t == 0) g_is64 = (any == 0u) ? 1 : 0;
  }

  // ---- load + convert A tile: 128 nodes x 64 c ----
#pragma unroll
  for (int i = 0; i < 8; i++) {
    int f4 = t + 256 * i;
    int row = f4 >> 4;
    int c4 = (f4 & 15) * 4;
    int node = node0 + row;
    float4 v = make_float4(0.f, 0.f, 0.f, 0.f);
    if (node < NN) v = *(const float4*)(feat + (size_t)node * DN + c4);
    __half2 h0 = __floats2half2_rn(v.x, v.y);
    __half2 h1 = __floats2half2_rn(v.z, v.w);
    uint2 pk;
    pk.x = *(unsigned*)&h0;
    pk.y = *(unsigned*)&h1;
    *(uint2*)(As + row * TS + c4) = pk;
  }
  // ---- load + convert B tile: 128 d x 64 c ----
#pragma unroll
  for (int i = 0; i < 8; i++) {
    int f4 = t + 256 * i;
    int d = f4 >> 4;
    int c4 = (f4 & 15) * 4;
    float4 v = *(const float4*)(W + (size_t)d * 320 + l * 64 + c4);
    __half2 h0 = __floats2half2_rn(v.x, v.y);
    __half2 h1 = __floats2half2_rn(v.z, v.w);
    uint2 pk;
    pk.x = *(unsigned*)&h0;
    pk.y = *(unsigned*)&h1;
    *(uint2*)(Bs + d * TS + c4) = pk;
  }
  __syncthreads();

  const int lane = t & 31;
  const int wid = t >> 5;
  const int m0 = (wid >> 1) * 32;
  const int n0 = (wid & 1) * 64;
  const int grp = lane >> 2;
  const int tig = lane & 3;

  float acc[2][8][4];
#pragma unroll
  for (int a = 0; a < 2; a++)
#pragma unroll
    for (int b = 0; b < 8; b++)
#pragma unroll
      for (int c = 0; c < 4; c++) acc[a][b][c] = 0.f;

#pragma unroll
  for (int ks = 0; ks < 4; ks++) {
    unsigned afr[2][4];
#pragma unroll
    for (int mt = 0; mt < 2; mt++) {
      const __half* ap = As + (size_t)(m0 + mt * 16 + grp) * TS + ks * 16 + tig * 2;
      afr[mt][0] = *(const unsigned*)(ap);
      afr[mt][1] = *(const unsigned*)(ap + 8 * TS);
      afr[mt][2] = *(const unsigned*)(ap + 8);
      afr[mt][3] = *(const unsigned*)(ap + 8 * TS + 8);
    }
#pragma unroll
    for (int nt = 0; nt < 8; nt++) {
      const __half* bp = Bs + (size_t)(n0 + nt * 8 + grp) * TS + ks * 16 + tig * 2;
      unsigned b0 = *(const unsigned*)(bp);
      unsigned b1 = *(const unsigned*)(bp + 8);
#pragma unroll
      for (int mt = 0; mt < 2; mt++)
        asm volatile(
            "mma.sync.aligned.m16n8k16.row.col.f32.f16.f16.f32 "
            "{%0,%1,%2,%3}, {%4,%5,%6,%7}, {%8,%9}, {%0,%1,%2,%3};"
            : "+f"(acc[mt][nt][0]), "+f"(acc[mt][nt][1]),
              "+f"(acc[mt][nt][2]), "+f"(acc[mt][nt][3])
            : "r"(afr[mt][0]), "r"(afr[mt][1]), "r"(afr[mt][2]), "r"(afr[mt][3]),
              "r"(b0), "r"(b1));
    }
  }

  // ---- epilogue: half2 stores straight to the proj table ----
#pragma unroll
  for (int mt = 0; mt < 2; mt++) {
    int nodeA = node0 + m0 + mt * 16 + grp;
    int nodeB = nodeA + 8;
#pragma unroll
    for (int nt = 0; nt < 8; nt++) {
      int d = n0 + nt * 8 + tig * 2;
      if (nodeA <= NN) {
        __half2 h = __floats2half2_rn(acc[mt][nt][0], acc[mt][nt][1]);
        *(__half2*)(g_proj + (size_t)nodeA * PROJ_COLS + l * DP + d) = h;
      }
      if (nodeB <= NN) {
        __half2 h = __floats2half2_rn(acc[mt][nt][2], acc[mt][nt][3]);
        *(__half2*)(g_proj + (size_t)nodeB * PROJ_COLS + l * DP + d) = h;
      }
    }
  }
}

// ---------------------------------------------------------------------------
// Phase 2: one warp per TWO (n,k) pairs -> 20 independent proj loads in
// flight per warp (2x MLP vs one pair).
//  - prologue: lanes 0..10 serve pair 0, lanes 16..26 serve pair 1
//  - out uses streaming evict-first stores
// ---------------------------------------------------------------------------
__global__ void __launch_bounds__(256, 3) phase2_gather(
    const void* __restrict__ paths_v,
    const void* __restrict__ eids_v,
    const float* __restrict__ weight,
    float* __restrict__ out) {
  const long long warp = (((long long)blockIdx.x * blockDim.x) + threadIdx.x) >> 5;
  const int lane = threadIdx.x & 31;
  const long long gw0 = warp * 2;                 // first (n,k) pair
  if (gw0 >= (long long)NN * KP) return;

  const int is64 = g_is64;

  // ---- parallel prologue for both pairs ----
  // lane layout: p = lane>>4 (pair), j = lane&15 (slot). j<6: path id; 6<=j<11: edge weight.
  const int pr = lane >> 4;
  const int j = lane & 15;
  const long long gw = gw0 + pr;                  // pair handled by this half-warp
  int pv = 0;
  float wv = 0.f;
  if (is64) {
    if (j < LP) {
      long long v = __ldg((const long long*)paths_v + gw * LP + j);
      v = v < 0 ? 0 : (v > NN ? NN : v);
      pv = (int)v;
    } else if (j < LP + LP - 1) {
      long long ev = __ldg((const long long*)eids_v + gw * (LP - 1) + (j - LP));
      ev = ev < 0 ? 0 : (ev > NE - 1 ? NE - 1 : ev);
      wv = __ldg(weight + ev);
    }
  } else {
    if (j < LP) {
      int v = __ldg((const int*)paths_v + gw * LP + j);
      v = v < 0 ? 0 : (v > NN ? NN : v);
      pv = v;
    } else if (j < LP + LP - 1) {
      int ev = __ldg((const int*)eids_v + gw * (LP - 1) + (j - LP));
      ev = ev < 0 ? 0 : (ev > NE - 1 ? NE - 1 : ev);
      wv = __ldg(weight + ev);
    }
  }

  int idx0[LP], idx1[LP];
  float w0[LP - 1], w1[LP - 1];
#pragma unroll
  for (int i = 0; i < LP; i++) {
    idx0[i] = __shfl_sync(0xFFFFFFFFu, pv, i);
    idx1[i] = __shfl_sync(0xFFFFFFFFu, pv, 16 + i);
  }
#pragma unroll
  for (int i = 0; i < LP - 1; i++) {
    w0[i] = __shfl_sync(0xFFFFFFFFu, wv, LP + i);
    w1[i] = __shfl_sync(0xFFFFFFFFu, wv, 16 + LP + i);
  }

  // ---- issue all 20 proj loads back-to-back (8 B/lane each) ----
  const int col = lane * 4;
  uint2 ra0[LP - 1], rb0[LP - 1], ra1[LP - 1], rb1[LP - 1];
#pragma unroll
  for (int i = 0; i < LP - 1; i++) {
    ra0[i] = __ldg((const uint2*)(g_proj + (size_t)idx0[i] * PROJ_COLS + i * DP + col));
    rb0[i] = __ldg((const uint2*)(g_proj + (size_t)idx0[i + 1] * PROJ_COLS + i * DP + col));
    ra1[i] = __ldg((const uint2*)(g_proj + (size_t)idx1[i] * PROJ_COLS + i * DP + col));
    rb1[i] = __ldg((const uint2*)(g_proj + (size_t)idx1[i + 1] * PROJ_COLS + i * DP + col));
  }

  float4 acc0 = make_float4(0.f, 0.f, 0.f, 0.f);
  float4 acc1 = make_float4(0.f, 0.f, 0.f, 0.f);
#pragma unroll
  for (int i = 0; i < LP - 1; i++) {
    float2 a01 = __half22float2(*(const __half2*)&ra0[i].x);
    float2 a23 = __half22float2(*(const __half2*)&ra0[i].y);
    float2 b01 = __half22float2(*(const __half2*)&rb0[i].x);
    float2 b23 = __half22float2(*(const __half2*)&rb0[i].y);
    acc0.x += a01.x + w0[i] * b01.x;
    acc0.y += a01.y + w0[i] * b01.y;
    acc0.z += a23.x + w0[i] * b23.x;
    acc0.w += a23.y + w0[i] * b23.y;
    a01 = __half22float2(*(const __half2*)&ra1[i].x);
    a23 = __half22float2(*(const __half2*)&ra1[i].y);
    b01 = __half22float2(*(const __half2*)&rb1[i].x);
    b23 = __half22float2(*(const __half2*)&rb1[i].y);
    acc1.x += a01.x + w1[i] * b01.x;
    acc1.y += a01.y + w1[i] * b01.y;
    acc1.z += a23.x + w1[i] * b23.x;
    acc1.w += a23.y + w1[i] * b23.y;
  }
  // streaming stores: evict-first
  {
    float* dst0 = out + gw0 * DP + col;
    asm volatile("st.global.cs.v4.f32 [%0], {%1,%2,%3,%4};"
                 :: "l"(dst0), "f"(acc0.x), "f"(acc0.y), "f"(acc0.z), "f"(acc0.w)
                 : "memory");
    float* dst1 = out + (gw0 + 1) * DP + col;
    asm volatile("st.global.cs.v4.f32 [%0], {%1,%2,%3,%4};"
                 :: "l"(dst1), "f"(acc1.x), "f"(acc1.y), "f"(acc1.z), "f"(acc1.w)
                 : "memory");
  }
}

// ---------------------------------------------------------------------------
// Launch. Inputs identified BY ELEMENT COUNT (all five distinct):
//   feat=3,200,000 f32 | weight=1,600,000 f32 | W=40,960 f32
//   paths=2,400,000 (i32/i64) | edge_ids=2,000,000 (i32/i64)
// ---------------------------------------------------------------------------
extern "C" void kernel_launch(void* const* d_in, const int* in_sizes, int n_in,
                              void* d_out, int out_size) {
  const float* feat = 0;
  const float* weight = 0;
  const float* W = 0;
  const void* paths = 0;
  const void* eids = 0;

  for (int i = 0; i < n_in; i++) {
    switch (in_sizes[i]) {
      case 3200000: feat   = (const float*)d_in[i]; break;
      case 1600000: weight = (const float*)d_in[i]; break;
      case 40960:   W      = (const float*)d_in[i]; break;
      case 2400000: paths  = d_in[i];               break;
      case 2000000: eids   = d_in[i];               break;
      default: break;
    }
  }
  if (!feat || !weight || !W || !paths || !eids) return;

  float* out = (float*)d_out;

  dim3 g1((NN + 1 + 127) / 128, 5);   // 391 x 5 CTAs, one l block per y
  phase1_mma<<<g1, 256>>>(feat, W, (const unsigned int*)paths);

  long long warps = ((long long)NN * KP + 1) / 2;     // 200,000 (2 pairs/warp)
  int blocks = (int)((warps * 32 + 255) / 256);       // 25,000
  phase2_gather<<<blocks, 256>>>(paths, eids, weight, out);
}

// round 13
// speedup vs baseline: 1.0489x; 1.0489x over previous
#include <cuda_runtime.h>
#include <cuda_fp16.h>

#define NN 50000         // n_node
#define KP 8             // k_path
#define LP 6             // l_path
#define DN 64            // d_node
#define DP 128           // d_path
#define NE 1600000       // n_edge
#define LSTRIDE ((size_t)(NN + 1) * DP)   // halves per l-table

// fp16 proj tables, layout [l][node][128]: 5 regions of 12.8 MB.
// proj_l[node][d] = sum_c W[d, l*64+c] * feat[node, c]; row NN = zeros.
__device__ __half g_proj[5 * LSTRIDE];
__device__ int g_is64;

// ---------------------------------------------------------------------------
// Phase 1 (tensor-core): fills g_proj. Per CTA: 128 nodes x 128 d, K=64,
// one l block (blockIdx.y). Block (0,0) warp 0 sniffs index dtype.
// ---------------------------------------------------------------------------
#define TS 72   // smem row stride in halves (64 + 8 pad) -> conflict-free frags

__global__ void __launch_bounds__(256, 2) phase1_mma(
    const float* __restrict__ feat, const float* __restrict__ W,
    const unsigned int* __restrict__ paths_raw) {
  __shared__ __half As[128 * TS];   // [node][c]
  __shared__ __half Bs[128 * TS];   // [d][c]

  const int t = threadIdx.x;
  const int node0 = blockIdx.x * 128;
  const int l = blockIdx.y;

  // ---- dtype sniff (one warp, one block): int64 data has all-zero high words ----
  if (blockIdx.x == 0 && blockIdx.y == 0 && t < 32) {
    unsigned v = paths_raw[t * 2 + 1];
    unsigned any = __ballot_sync(0xFFFFFFFFu, v != 0u);
    if (t == 0) g_is64 = (any == 0u) ? 1 : 0;
  }

  // ---- load + convert A tile: 128 nodes x 64 c ----
#pragma unroll
  for (int i = 0; i < 8; i++) {
    int f4 = t + 256 * i;
    int row = f4 >> 4;
    int c4 = (f4 & 15) * 4;
    int node = node0 + row;
    float4 v = make_float4(0.f, 0.f, 0.f, 0.f);
    if (node < NN) v = *(const float4*)(feat + (size_t)node * DN + c4);
    __half2 h0 = __floats2half2_rn(v.x, v.y);
    __half2 h1 = __floats2half2_rn(v.z, v.w);
    uint2 pk;
    pk.x = *(unsigned*)&h0;
    pk.y = *(unsigned*)&h1;
    *(uint2*)(As + row * TS + c4) = pk;
  }
  // ---- load + convert B tile: 128 d x 64 c ----
#pragma unroll
  for (int i = 0; i < 8; i++) {
    int f4 = t + 256 * i;
    int d = f4 >> 4;
    int c4 = (f4 & 15) * 4;
    float4 v = *(const float4*)(W + (size_t)d * 320 + l * 64 + c4);
    __half2 h0 = __floats2half2_rn(v.x, v.y);
    __half2 h1 = __floats2half2_rn(v.z, v.w);
    uint2 pk;
    pk.x = *(unsigned*)&h0;
    pk.y = *(unsigned*)&h1;
    *(uint2*)(Bs + d * TS + c4) = pk;
  }
  __syncthreads();

  const int lane = t & 31;
  const int wid = t >> 5;
  const int m0 = (wid >> 1) * 32;
  const int n0 = (wid & 1) * 64;
  const int grp = lane >> 2;
  const int tig = lane & 3;

  float acc[2][8][4];
#pragma unroll
  for (int a = 0; a < 2; a++)
#pragma unroll
    for (int b = 0; b < 8; b++)
#pragma unroll
      for (int c = 0; c < 4; c++) acc[a][b][c] = 0.f;

#pragma unroll
  for (int ks = 0; ks < 4; ks++) {
    unsigned afr[2][4];
#pragma unroll
    for (int mt = 0; mt < 2; mt++) {
      const __half* ap = As + (size_t)(m0 + mt * 16 + grp) * TS + ks * 16 + tig * 2;
      afr[mt][0] = *(const unsigned*)(ap);
      afr[mt][1] = *(const unsigned*)(ap + 8 * TS);
      afr[mt][2] = *(const unsigned*)(ap + 8);
      afr[mt][3] = *(const unsigned*)(ap + 8 * TS + 8);
    }
#pragma unroll
    for (int nt = 0; nt < 8; nt++) {
      const __half* bp = Bs + (size_t)(n0 + nt * 8 + grp) * TS + ks * 16 + tig * 2;
      unsigned b0 = *(const unsigned*)(bp);
      unsigned b1 = *(const unsigned*)(bp + 8);
#pragma unroll
      for (int mt = 0; mt < 2; mt++)
        asm volatile(
            "mma.sync.aligned.m16n8k16.row.col.f32.f16.f16.f32 "
            "{%0,%1,%2,%3}, {%4,%5,%6,%7}, {%8,%9}, {%0,%1,%2,%3};"
            : "+f"(acc[mt][nt][0]), "+f"(acc[mt][nt][1]),
              "+f"(acc[mt][nt][2]), "+f"(acc[mt][nt][3])
            : "r"(afr[mt][0]), "r"(afr[mt][1]), "r"(afr[mt][2]), "r"(afr[mt][3]),
              "r"(b0), "r"(b1));
    }
  }

  // ---- epilogue: half2 stores to the l-partitioned proj table ----
  __half* projL = g_proj + (size_t)l * LSTRIDE;
#pragma unroll
  for (int mt = 0; mt < 2; mt++) {
    int nodeA = node0 + m0 + mt * 16 + grp;
    int nodeB = nodeA + 8;
#pragma unroll
    for (int nt = 0; nt < 8; nt++) {
      int d = n0 + nt * 8 + tig * 2;
      if (nodeA <= NN) {
        __half2 h = __floats2half2_rn(acc[mt][nt][0], acc[mt][nt][1]);
        *(__half2*)(projL + (size_t)nodeA * DP + d) = h;
      }
      if (nodeB <= NN) {
        __half2 h = __floats2half2_rn(acc[mt][nt][2], acc[mt][nt][3]);
        *(__half2*)(projL + (size_t)nodeB * DP + d) = h;
      }
    }
  }
}

// ---------------------------------------------------------------------------
// Phase 2 (R11 config): one warp per (n,k).
//  - lane-parallel index/weight prologue + shfl broadcast
//  - proj gathers from l-partitioned regions (12.8 MB locality per stream)
//  - streaming evict-first output stores
// ---------------------------------------------------------------------------
__device__ __forceinline__ unsigned long long make_evict_last_policy() {
  unsigned long long pol;
  asm("createpolicy.fractional.L2::evict_last.b64 %0, 1.0;" : "=l"(pol));
  return pol;
}

__device__ __forceinline__ uint2 ldg_el_u2(const void* p, unsigned long long pol) {
  uint2 r;
  asm volatile("ld.global.nc.L2::cache_hint.v2.u32 {%0,%1}, [%2], %3;"
               : "=r"(r.x), "=r"(r.y) : "l"(p), "l"(pol));
  return r;
}

__global__ void __launch_bounds__(256) phase2_gather(
    const void* __restrict__ paths_v,
    const void* __restrict__ eids_v,
    const float* __restrict__ weight,
    float* __restrict__ out) {
  const long long gw = (((long long)blockIdx.x * blockDim.x) + threadIdx.x) >> 5;
  const int lane = threadIdx.x & 31;
  if (gw >= (long long)NN * KP) return;

  const int is64 = g_is64;
  const unsigned long long pol = make_evict_last_policy();

  // ---- parallel prologue: lanes 0..5 -> path ids, lanes 6..10 -> edge+weight ----
  int pv = 0;
  float wv = 0.f;
  if (is64) {
    if (lane < LP) {
      long long v = __ldg((const long long*)paths_v + gw * LP + lane);
      v = v < 0 ? 0 : (v > NN ? NN : v);
      pv = (int)v;
    } else if (lane < LP + LP - 1) {
      long long ev = __ldg((const long long*)eids_v + gw * (LP - 1) + (lane - LP));
      ev = ev < 0 ? 0 : (ev > NE - 1 ? NE - 1 : ev);
      float t;
      asm volatile("ld.global.nc.L2::cache_hint.f32 %0, [%1], %2;"
                   : "=f"(t) : "l"(weight + ev), "l"(pol));
      wv = t;
    }
  } else {
    if (lane < LP) {
      int v = __ldg((const int*)paths_v + gw * LP + lane);
      v = v < 0 ? 0 : (v > NN ? NN : v);
      pv = v;
    } else if (lane < LP + LP - 1) {
      int ev = __ldg((const int*)eids_v + gw * (LP - 1) + (lane - LP));
      ev = ev < 0 ? 0 : (ev > NE - 1 ? NE - 1 : ev);
      float t;
      asm volatile("ld.global.nc.L2::cache_hint.f32 %0, [%1], %2;"
                   : "=f"(t) : "l"(weight + ev), "l"(pol));
      wv = t;
    }
  }

  int idx[LP];
  float w[LP - 1];
#pragma unroll
  for (int i = 0; i < LP; i++) idx[i] = __shfl_sync(0xFFFFFFFFu, pv, i);
#pragma unroll
  for (int i = 0; i < LP - 1; i++) w[i] = __shfl_sync(0xFFFFFFFFu, wv, LP + i);

  // ---- gather 10 proj vectors from the 5 l-regions (8 B/lane each) ----
  const int col = lane * 4;
  uint2 ra[LP - 1], rb[LP - 1];
#pragma unroll
  for (int i = 0; i < LP - 1; i++) {
    const __half* projL = g_proj + (size_t)i * LSTRIDE;
    ra[i] = ldg_el_u2(projL + (size_t)idx[i] * DP + col, pol);
    rb[i] = ldg_el_u2(projL + (size_t)idx[i + 1] * DP + col, pol);
  }

  float4 acc = make_float4(0.f, 0.f, 0.f, 0.f);
#pragma unroll
  for (int i = 0; i < LP - 1; i++) {
    float2 a01 = __half22float2(*(const __half2*)&ra[i].x);
    float2 a23 = __half22float2(*(const __half2*)&ra[i].y);
    float2 b01 = __half22float2(*(const __half2*)&rb[i].x);
    float2 b23 = __half22float2(*(const __half2*)&rb[i].y);
    acc.x += a01.x + w[i] * b01.x;
    acc.y += a01.y + w[i] * b01.y;
    acc.z += a23.x + w[i] * b23.x;
    acc.w += a23.y + w[i] * b23.y;
  }
  // streaming store: evict-first
  float* dst = out + gw * DP + col;
  asm volatile("st.global.cs.v4.f32 [%0], {%1,%2,%3,%4};"
               :: "l"(dst), "f"(acc.x), "f"(acc.y), "f"(acc.z), "f"(acc.w)
               : "memory");
}

// ---------------------------------------------------------------------------
// Launch. Inputs identified BY ELEMENT COUNT (all five distinct):
//   feat=3,200,000 f32 | weight=1,600,000 f32 | W=40,960 f32
//   paths=2,400,000 (i32/i64) | edge_ids=2,000,000 (i32/i64)
// ---------------------------------------------------------------------------
extern "C" void kernel_launch(void* const* d_in, const int* in_sizes, int n_in,
                              void* d_out, int out_size) {
  const float* feat = 0;
  const float* weight = 0;
  const float* W = 0;
  const void* paths = 0;
  const void* eids = 0;

  for (int i = 0; i < n_in; i++) {
    switch (in_sizes[i]) {
      case 3200000: feat   = (const float*)d_in[i]; break;
      case 1600000: weight = (const float*)d_in[i]; break;
      case 40960:   W      = (const float*)d_in[i]; break;
      case 2400000: paths  = d_in[i];               break;
      case 2000000: eids   = d_in[i];               break;
      default: break;
    }
  }
  if (!feat || !weight || !W || !paths || !eids) return;

  float* out = (float*)d_out;

  dim3 g1((NN + 1 + 127) / 128, 5);   // 391 x 5 CTAs, one l block per y
  phase1_mma<<<g1, 256>>>(feat, W, (const unsigned int*)paths);

  long long warps = (long long)NN * KP;               // 400,000
  int blocks = (int)((warps * 32 + 255) / 256);       // 50,000
  phase2_gather<<<blocks, 256>>>(paths, eids, weight, out);
}